// round 10
// baseline (speedup 1.0000x reference)
#include <cuda_runtime.h>
#include <cuda_bf16.h>
#include <cstdint>

// Problem constants
#define B_SZ   4096
#define DIMK   512
#define MN_SZ  4096
#define GRID_N 64
#define BM 128
#define BN 128
#define NTILES (MN_SZ / BN)        // 32 tiles -> 64 candidates/row
#define KITERS (DIMK / 32)         // 16

// smem geometry: 4 arrays (Ahi, Alo, Whi, Wlo), 128 rows x 32 bf16, stride 80B
#define STRIDE_B 80
#define ARR_SZ   (128 * STRIDE_B)   // 10240
#define STAGE_SZ (4 * ARR_SZ)       // 40960
#define NSTAGE   4
#define SMEM_TOTAL (NSTAGE * STAGE_SZ)   // 163840

// ---- device scratch -------------------------------------------------------
__device__ float g_w2[MN_SZ];
__device__ __align__(16) __nv_bfloat16 g_Ahi[B_SZ * DIMK];
__device__ __align__(16) __nv_bfloat16 g_Alo[B_SZ * DIMK];
__device__ __align__(16) __nv_bfloat16 g_Whi[MN_SZ * DIMK];
__device__ __align__(16) __nv_bfloat16 g_Wlo[MN_SZ * DIMK];
__device__ float g_tv[B_SZ * NTILES * 2];
__device__ int   g_ti[B_SZ * NTILES * 2];

// ---- helpers --------------------------------------------------------------
__device__ __forceinline__ uint32_t smem_u32(const void* p) {
    uint32_t a;
    asm("{ .reg .u64 t; cvta.to.shared.u64 t, %1; cvt.u32.u64 %0, t; }" : "=r"(a) : "l"(p));
    return a;
}
__device__ __forceinline__ void cp16(uint32_t dst, const void* src) {
    asm volatile("cp.async.cg.shared.global [%0], [%1], 16;" :: "r"(dst), "l"(src));
}
#define CP_COMMIT() asm volatile("cp.async.commit_group;" ::: "memory")
#define CP_WAIT2()  asm volatile("cp.async.wait_group 2;" ::: "memory")
#define CP_WAIT0()  asm volatile("cp.async.wait_group 0;" ::: "memory")

__device__ __forceinline__ void ldsm4(uint32_t* r, uint32_t a) {
    asm volatile("ldmatrix.sync.aligned.m8n8.x4.shared.b16 {%0,%1,%2,%3}, [%4];"
                 : "=r"(r[0]), "=r"(r[1]), "=r"(r[2]), "=r"(r[3]) : "r"(a));
}
__device__ __forceinline__ void mma16816(float* c, const uint32_t* a, const uint32_t* b) {
    asm volatile("mma.sync.aligned.m16n8k16.row.col.f32.bf16.bf16.f32 "
                 "{%0,%1,%2,%3}, {%4,%5,%6,%7}, {%8,%9}, {%0,%1,%2,%3};"
                 : "+f"(c[0]), "+f"(c[1]), "+f"(c[2]), "+f"(c[3])
                 : "r"(a[0]), "r"(a[1]), "r"(a[2]), "r"(a[3]), "r"(b[0]), "r"(b[1]));
}
__device__ __forceinline__ void merge2(float& v1, int& i1, float& v2, int& i2,
                                       float ov, int oi) {
    if (ov < v1 || (ov == v1 && oi < i1)) { v2 = v1; i2 = i1; v1 = ov; i1 = oi; }
    else if (ov < v2 || (ov == v2 && oi < i2)) { v2 = ov; i2 = oi; }
}

// ---------------------------------------------------------------------------
// Kernel 0: split fp32 -> bf16 hi/lo, fused w2 (each block = exactly 2 rows)
// ---------------------------------------------------------------------------
__global__ void split_kernel(const float* __restrict__ a, const float* __restrict__ w) {
    __shared__ float s_part[8];
    const int tid = threadIdx.x;
    int i = blockIdx.x * 256 + tid;                   // float4 index
    float4 x = ((const float4*)a)[i];
    float4 y = ((const float4*)w)[i];
    __nv_bfloat16 h0 = __float2bfloat16(x.x), h1 = __float2bfloat16(x.y);
    __nv_bfloat16 h2 = __float2bfloat16(x.z), h3 = __float2bfloat16(x.w);
    ((__nv_bfloat162*)g_Ahi)[i * 2 + 0] = __nv_bfloat162(h0, h1);
    ((__nv_bfloat162*)g_Ahi)[i * 2 + 1] = __nv_bfloat162(h2, h3);
    ((__nv_bfloat162*)g_Alo)[i * 2 + 0] = __nv_bfloat162(
        __float2bfloat16(x.x - __bfloat162float(h0)), __float2bfloat16(x.y - __bfloat162float(h1)));
    ((__nv_bfloat162*)g_Alo)[i * 2 + 1] = __nv_bfloat162(
        __float2bfloat16(x.z - __bfloat162float(h2)), __float2bfloat16(x.w - __bfloat162float(h3)));
    __nv_bfloat16 g0 = __float2bfloat16(y.x), g1 = __float2bfloat16(y.y);
    __nv_bfloat16 g2 = __float2bfloat16(y.z), g3 = __float2bfloat16(y.w);
    ((__nv_bfloat162*)g_Whi)[i * 2 + 0] = __nv_bfloat162(g0, g1);
    ((__nv_bfloat162*)g_Whi)[i * 2 + 1] = __nv_bfloat162(g2, g3);
    ((__nv_bfloat162*)g_Wlo)[i * 2 + 0] = __nv_bfloat162(
        __float2bfloat16(y.x - __bfloat162float(g0)), __float2bfloat16(y.y - __bfloat162float(g1)));
    ((__nv_bfloat162*)g_Wlo)[i * 2 + 1] = __nv_bfloat162(
        __float2bfloat16(y.z - __bfloat162float(g2)), __float2bfloat16(y.w - __bfloat162float(g3)));

    // fused w2: block covers weight rows 2*blk (tids 0..127) and 2*blk+1 (128..255)
    float s = y.x * y.x + y.y * y.y + y.z * y.z + y.w * y.w;
    #pragma unroll
    for (int o = 16; o > 0; o >>= 1) s += __shfl_down_sync(0xffffffffu, s, o);
    if ((tid & 31) == 0) s_part[tid >> 5] = s;
    __syncthreads();
    if (tid == 0)
        g_w2[blockIdx.x * 2]     = s_part[0] + s_part[1] + s_part[2] + s_part[3];
    else if (tid == 128)
        g_w2[blockIdx.x * 2 + 1] = s_part[4] + s_part[5] + s_part[6] + s_part[7];
}

// ---------------------------------------------------------------------------
// Kernel 1: bf16x3 mma.sync GEMM (128x128 tile), 4-stage pipeline + top-2
// ---------------------------------------------------------------------------
__device__ __forceinline__ void load_stage(uint32_t smBase, int buf, int kIter,
                                           int rowBase, int colBase, int t) {
    uint32_t stage = smBase + buf * STAGE_SZ;
    #pragma unroll
    for (int i = 0; i < 2; i++) {
        int cid = i * 256 + t;          // 512 16B-chunks per array
        int r = cid >> 2, c = cid & 3;
        uint32_t doff = (uint32_t)(r * STRIDE_B + c * 16);
        size_t gA = (size_t)(rowBase + r) * DIMK + kIter * 32 + c * 8;
        size_t gW = (size_t)(colBase + r) * DIMK + kIter * 32 + c * 8;
        cp16(stage + doff,              &g_Ahi[gA]);
        cp16(stage + ARR_SZ + doff,     &g_Alo[gA]);
        cp16(stage + 2 * ARR_SZ + doff, &g_Whi[gW]);
        cp16(stage + 3 * ARR_SZ + doff, &g_Wlo[gW]);
    }
}

__global__ void __launch_bounds__(256)
gemm_mma_kernel() {
    extern __shared__ char smem[];
    const uint32_t sm = smem_u32(smem);
    const int t    = threadIdx.x;
    const int wid  = t >> 5;
    const int lane = t & 31;
    const int warpM = (wid & 3) * 32;       // 4 warps over M
    const int warpN = (wid >> 2) * 64;      // 2 warps over N
    const int rowBase = blockIdx.y * BM;
    const int colBase = blockIdx.x * BN;

    float acc[2][8][4];
    #pragma unroll
    for (int a = 0; a < 2; a++)
        #pragma unroll
        for (int b = 0; b < 8; b++)
            #pragma unroll
            for (int q = 0; q < 4; q++) acc[a][b][q] = 0.f;

    load_stage(sm, 0, 0, rowBase, colBase, t); CP_COMMIT();
    load_stage(sm, 1, 1, rowBase, colBase, t); CP_COMMIT();
    load_stage(sm, 2, 2, rowBase, colBase, t); CP_COMMIT();

    for (int k = 0; k < KITERS; k++) {
        CP_WAIT2();
        __syncthreads();   // stage k ready; also: everyone done reading stage k-1's buffer

        const uint32_t aHi = sm + (k & 3) * STAGE_SZ;
        const uint32_t bHi = aHi + 2 * ARR_SZ;

        #pragma unroll
        for (int ks = 0; ks < 2; ks++) {
            uint32_t ah[2][4], al[2][4];
            #pragma unroll
            for (int mf = 0; mf < 2; mf++) {
                uint32_t ao = (uint32_t)((warpM + mf * 16 + (lane & 15)) * STRIDE_B
                                         + ks * 32 + (lane >> 4) * 16);
                ldsm4(ah[mf], aHi + ao);
                ldsm4(al[mf], aHi + ARR_SZ + ao);
            }
            #pragma unroll
            for (int np = 0; np < 4; np++) {
                uint32_t bh[4], bl[4];
                int n = warpN + np * 16 + (lane & 7) + ((lane >> 4) & 1) * 8;
                uint32_t bo = (uint32_t)(n * STRIDE_B + ks * 32 + ((lane >> 3) & 1) * 16);
                ldsm4(bh, bHi + bo);
                ldsm4(bl, bHi + ARR_SZ + bo);
                #pragma unroll
                for (int mf = 0; mf < 2; mf++) {
                    #pragma unroll
                    for (int nn = 0; nn < 2; nn++) {
                        float* C = acc[mf][np * 2 + nn];
                        mma16816(C, ah[mf], &bh[nn * 2]);   // hi*hi
                        mma16816(C, ah[mf], &bl[nn * 2]);   // hi*lo
                        mma16816(C, al[mf], &bh[nn * 2]);   // lo*hi
                    }
                }
            }
        }
        // load stage k+3 into buffer (k+3)&3 == (k-1)&3: safe, all warps passed
        // this iter's barrier, i.e. finished computing stage k-1.
        if (k + 3 < KITERS) load_stage(sm, (k + 3) & 3, k + 3, rowBase, colBase, t);
        CP_COMMIT();
    }

    // ---- epilogue: d2 = w2 - 2*dot, per-row top-2 within this 128-col tile
    CP_WAIT0();
    __syncthreads();
    float* candV = (float*)smem;            // [128][4] (2 n-warps x 2)
    int*   candI = (int*)(smem + 2048);

    #pragma unroll
    for (int mf = 0; mf < 2; mf++) {
        #pragma unroll
        for (int half = 0; half < 2; half++) {
            float v1 = __int_as_float(0x7f800000), v2 = v1;
            int   i1 = 0x7fffffff,                i2 = i1;
            #pragma unroll
            for (int nf = 0; nf < 8; nf++) {
                #pragma unroll
                for (int q = 0; q < 2; q++) {
                    int col = colBase + warpN + nf * 8 + (lane & 3) * 2 + q;
                    float v = g_w2[col] - 2.f * acc[mf][nf][half * 2 + q];
                    merge2(v1, i1, v2, i2, v, col);
                }
            }
            #pragma unroll
            for (int x = 1; x <= 2; x <<= 1) {
                float ov1 = __shfl_xor_sync(0xffffffffu, v1, x);
                int   oi1 = __shfl_xor_sync(0xffffffffu, i1, x);
                float ov2 = __shfl_xor_sync(0xffffffffu, v2, x);
                int   oi2 = __shfl_xor_sync(0xffffffffu, i2, x);
                merge2(v1, i1, v2, i2, ov1, oi1);
                merge2(v1, i1, v2, i2, ov2, oi2);
            }
            if ((lane & 3) == 0) {
                int rowL = warpM + mf * 16 + half * 8 + (lane >> 2);
                int nw   = wid >> 2;
                candV[rowL * 4 + nw * 2 + 0] = v1;
                candI[rowL * 4 + nw * 2 + 0] = i1;
                candV[rowL * 4 + nw * 2 + 1] = v2;
                candI[rowL * 4 + nw * 2 + 1] = i2;
            }
        }
    }
    __syncthreads();

    if (t < BM) {
        float v1 = candV[t * 4], v2 = __int_as_float(0x7f800000);
        int   i1 = candI[t * 4], i2 = 0x7fffffff;
        #pragma unroll
        for (int s = 1; s < 4; s++) merge2(v1, i1, v2, i2, candV[t * 4 + s], candI[t * 4 + s]);
        int row = rowBase + t;
        int o = row * (NTILES * 2) + blockIdx.x * 2;
        g_tv[o] = v1;     g_ti[o] = i1;
        g_tv[o + 1] = v2; g_ti[o + 1] = i2;
    }
}

// ---------------------------------------------------------------------------
// Kernel 2: 4 batch rows per block. Warp w: reduce 64 candidates of row w ->
// approx top-2 -> exact fp32 recheck -> BMU. Then 256 threads build 4 pairs of
// Gaussian tables and stream 4 output rows (16KB).
// ---------------------------------------------------------------------------
__global__ void __launch_bounds__(256)
output_kernel(float* __restrict__ out,
              const float* __restrict__ batch,
              const float* __restrict__ weights,
              const int* __restrict__ decay_p,
              const int* __restrict__ it_p) {
    __shared__ float gx[4][GRID_N];
    __shared__ float gy[4][GRID_N];
    __shared__ int   s_bmu[4];

    const int t    = threadIdx.x;
    const int wid  = t >> 5;
    const int lane = t & 31;

    if (wid < 4) {
        const int b = blockIdx.x * 4 + wid;
        float v1 = g_tv[b * 64 + lane];
        int   i1 = g_ti[b * 64 + lane];
        float v2 = g_tv[b * 64 + 32 + lane];
        int   i2 = g_ti[b * 64 + 32 + lane];
        if (v2 < v1 || (v2 == v1 && i2 < i1)) {
            float tv = v1; v1 = v2; v2 = tv;
            int   ti = i1; i1 = i2; i2 = ti;
        }
        #pragma unroll
        for (int o = 16; o > 0; o >>= 1) {
            float ov1 = __shfl_xor_sync(0xffffffffu, v1, o);
            int   oi1 = __shfl_xor_sync(0xffffffffu, i1, o);
            float ov2 = __shfl_xor_sync(0xffffffffu, v2, o);
            int   oi2 = __shfl_xor_sync(0xffffffffu, i2, o);
            merge2(v1, i1, v2, i2, ov1, oi1);
            merge2(v1, i1, v2, i2, ov2, oi2);
        }
        // exact fp32 recheck of the two candidates
        const float* br = batch + (size_t)b * DIMK;
        const float* w0 = weights + (size_t)i1 * DIMK;
        const float* w1 = weights + (size_t)i2 * DIMK;
        float s0 = 0.f, s1 = 0.f;
        #pragma unroll 4
        for (int k = lane; k < DIMK; k += 32) {
            float x = br[k];
            s0 += x * w0[k];
            s1 += x * w1[k];
        }
        #pragma unroll
        for (int o = 16; o > 0; o >>= 1) {
            s0 += __shfl_down_sync(0xffffffffu, s0, o);
            s1 += __shfl_down_sync(0xffffffffu, s1, o);
        }
        if (lane == 0) {
            float d0 = g_w2[i1] - 2.f * s0;
            float d1 = g_w2[i2] - 2.f * s1;
            s_bmu[wid] = (d1 < d0 || (d1 == d0 && i2 < i1)) ? i2 : i1;
        }
    }
    __syncthreads();

    const float itv = (float)it_p[0];
    const float dcv = (float)decay_p[0];
    const float lr  = __expf(-itv / dcv);
    const float sig = 32.0f * lr;
    const float inv = 1.0f / (sig * sig);

    // 512 table entries (4 rows x 128), 2 per thread
    #pragma unroll
    for (int e = t; e < 512; e += 256) {
        int r = e >> 7;
        int x = e & 127;
        int bmu = s_bmu[r];
        if (x < GRID_N) {
            float d = (float)(x - (bmu >> 6));
            gx[r][x] = __expf(-d * d * inv);
        } else {
            int j = x - GRID_N;
            float d = (float)(j - (bmu & 63));
            gy[r][j] = __expf(-d * d * inv);
        }
    }
    __syncthreads();

    // stores: thread handles row r = t>>6, grid-row i = t&63 -> 64 floats
    const int r = t >> 6;
    const int i = t & 63;
    const float gxi = gx[r][i];
    float4* o4 = (float4*)(out + (size_t)(blockIdx.x * 4 + r) * MN_SZ + i * GRID_N);
    #pragma unroll
    for (int q = 0; q < 16; q++) {
        float4 v;
        v.x = gxi * gy[r][q * 4 + 0];
        v.y = gxi * gy[r][q * 4 + 1];
        v.z = gxi * gy[r][q * 4 + 2];
        v.w = gxi * gy[r][q * 4 + 3];
        o4[q] = v;
    }
}

// ---------------------------------------------------------------------------
extern "C" void kernel_launch(void* const* d_in, const int* in_sizes, int n_in,
                              void* d_out, int out_size) {
    const float* batch   = (const float*)d_in[0];
    const float* weights = (const float*)d_in[1];
    const int* decay = (const int*)d_in[3];
    const int* it    = (const int*)d_in[4];
    float* out = (float*)d_out;

    cudaFuncSetAttribute(gemm_mma_kernel, cudaFuncAttributeMaxDynamicSharedMemorySize, SMEM_TOTAL);

    split_kernel<<<B_SZ * DIMK / 4 / 256, 256>>>(batch, weights);
    dim3 g(MN_SZ / BN, B_SZ / BM);     // (32, 32)
    gemm_mma_kernel<<<g, 256, SMEM_TOTAL>>>();
    output_kernel<<<B_SZ / 4, 256>>>(out, batch, weights, decay, it);
}

// round 11
// speedup vs baseline: 1.0637x; 1.0637x over previous
#include <cuda_runtime.h>
#include <cuda_bf16.h>
#include <cstdint>

// Problem constants
#define B_SZ   4096
#define DIMK   512
#define MN_SZ  4096
#define GRID_N 64
#define BM 128
#define BN 128
#define NTILES (MN_SZ / BN)        // 32 tiles -> 64 candidates/row
#define KC     64                  // K per stage (64 bf16 = 128B rows)
#define KITERS (DIMK / KC)         // 8

// smem geometry: 4 arrays (Ahi, Alo, Whi, Wlo), 128 rows x 64 bf16, stride 144B
// 144B = 36 words; 36 mod 32 = 4 -> ldmatrix rows hit banks 0,4,..,28: conflict-free
#define STRIDE_B 144
#define ARR_SZ   (128 * STRIDE_B)   // 18432
#define STAGE_SZ (4 * ARR_SZ)       // 73728
#define SMEM_TOTAL (2 * STAGE_SZ)   // 147456

// ---- device scratch -------------------------------------------------------
__device__ float g_w2[MN_SZ];
__device__ __align__(16) __nv_bfloat16 g_Ahi[B_SZ * DIMK];
__device__ __align__(16) __nv_bfloat16 g_Alo[B_SZ * DIMK];
__device__ __align__(16) __nv_bfloat16 g_Whi[MN_SZ * DIMK];
__device__ __align__(16) __nv_bfloat16 g_Wlo[MN_SZ * DIMK];
__device__ float g_tv[B_SZ * NTILES * 2];
__device__ int   g_ti[B_SZ * NTILES * 2];

// ---- helpers --------------------------------------------------------------
__device__ __forceinline__ uint32_t smem_u32(const void* p) {
    uint32_t a;
    asm("{ .reg .u64 t; cvta.to.shared.u64 t, %1; cvt.u32.u64 %0, t; }" : "=r"(a) : "l"(p));
    return a;
}
__device__ __forceinline__ void cp16(uint32_t dst, const void* src) {
    asm volatile("cp.async.cg.shared.global [%0], [%1], 16;" :: "r"(dst), "l"(src));
}
#define CP_COMMIT() asm volatile("cp.async.commit_group;" ::: "memory")
#define CP_WAIT1()  asm volatile("cp.async.wait_group 1;" ::: "memory")
#define CP_WAIT0()  asm volatile("cp.async.wait_group 0;" ::: "memory")

__device__ __forceinline__ void ldsm4(uint32_t* r, uint32_t a) {
    asm volatile("ldmatrix.sync.aligned.m8n8.x4.shared.b16 {%0,%1,%2,%3}, [%4];"
                 : "=r"(r[0]), "=r"(r[1]), "=r"(r[2]), "=r"(r[3]) : "r"(a));
}
__device__ __forceinline__ void mma16816(float* c, const uint32_t* a, const uint32_t* b) {
    asm volatile("mma.sync.aligned.m16n8k16.row.col.f32.bf16.bf16.f32 "
                 "{%0,%1,%2,%3}, {%4,%5,%6,%7}, {%8,%9}, {%0,%1,%2,%3};"
                 : "+f"(c[0]), "+f"(c[1]), "+f"(c[2]), "+f"(c[3])
                 : "r"(a[0]), "r"(a[1]), "r"(a[2]), "r"(a[3]), "r"(b[0]), "r"(b[1]));
}
__device__ __forceinline__ void merge2(float& v1, int& i1, float& v2, int& i2,
                                       float ov, int oi) {
    if (ov < v1 || (ov == v1 && oi < i1)) { v2 = v1; i2 = i1; v1 = ov; i1 = oi; }
    else if (ov < v2 || (ov == v2 && oi < i2)) { v2 = ov; i2 = oi; }
}

// ---------------------------------------------------------------------------
// Kernel 0: split fp32 -> bf16 hi/lo, fused w2 (each block = exactly 2 rows)
// ---------------------------------------------------------------------------
__global__ void split_kernel(const float* __restrict__ a, const float* __restrict__ w) {
    __shared__ float s_part[8];
    const int tid = threadIdx.x;
    int i = blockIdx.x * 256 + tid;                   // float4 index
    float4 x = ((const float4*)a)[i];
    float4 y = ((const float4*)w)[i];
    __nv_bfloat16 h0 = __float2bfloat16(x.x), h1 = __float2bfloat16(x.y);
    __nv_bfloat16 h2 = __float2bfloat16(x.z), h3 = __float2bfloat16(x.w);
    ((__nv_bfloat162*)g_Ahi)[i * 2 + 0] = __nv_bfloat162(h0, h1);
    ((__nv_bfloat162*)g_Ahi)[i * 2 + 1] = __nv_bfloat162(h2, h3);
    ((__nv_bfloat162*)g_Alo)[i * 2 + 0] = __nv_bfloat162(
        __float2bfloat16(x.x - __bfloat162float(h0)), __float2bfloat16(x.y - __bfloat162float(h1)));
    ((__nv_bfloat162*)g_Alo)[i * 2 + 1] = __nv_bfloat162(
        __float2bfloat16(x.z - __bfloat162float(h2)), __float2bfloat16(x.w - __bfloat162float(h3)));
    __nv_bfloat16 g0 = __float2bfloat16(y.x), g1 = __float2bfloat16(y.y);
    __nv_bfloat16 g2 = __float2bfloat16(y.z), g3 = __float2bfloat16(y.w);
    ((__nv_bfloat162*)g_Whi)[i * 2 + 0] = __nv_bfloat162(g0, g1);
    ((__nv_bfloat162*)g_Whi)[i * 2 + 1] = __nv_bfloat162(g2, g3);
    ((__nv_bfloat162*)g_Wlo)[i * 2 + 0] = __nv_bfloat162(
        __float2bfloat16(y.x - __bfloat162float(g0)), __float2bfloat16(y.y - __bfloat162float(g1)));
    ((__nv_bfloat162*)g_Wlo)[i * 2 + 1] = __nv_bfloat162(
        __float2bfloat16(y.z - __bfloat162float(g2)), __float2bfloat16(y.w - __bfloat162float(g3)));

    float s = y.x * y.x + y.y * y.y + y.z * y.z + y.w * y.w;
    #pragma unroll
    for (int o = 16; o > 0; o >>= 1) s += __shfl_down_sync(0xffffffffu, s, o);
    if ((tid & 31) == 0) s_part[tid >> 5] = s;
    __syncthreads();
    if (tid == 0)
        g_w2[blockIdx.x * 2]     = s_part[0] + s_part[1] + s_part[2] + s_part[3];
    else if (tid == 128)
        g_w2[blockIdx.x * 2 + 1] = s_part[4] + s_part[5] + s_part[6] + s_part[7];
}

// ---------------------------------------------------------------------------
// Kernel 1: bf16x3 mma.sync GEMM (128x128 tile), 2-stage K=64 pipeline + top-2
// ---------------------------------------------------------------------------
__device__ __forceinline__ void load_stage(uint32_t smBase, int buf, int kIter,
                                           int rowBase, int colBase, int t) {
    uint32_t stage = smBase + buf * STAGE_SZ;
    #pragma unroll
    for (int i = 0; i < 4; i++) {
        int cid = i * 256 + t;          // 1024 16B-chunks per array
        int r = cid >> 3, c = cid & 7;
        uint32_t doff = (uint32_t)(r * STRIDE_B + c * 16);
        size_t gA = (size_t)(rowBase + r) * DIMK + kIter * KC + c * 8;
        size_t gW = (size_t)(colBase + r) * DIMK + kIter * KC + c * 8;
        cp16(stage + doff,              &g_Ahi[gA]);
        cp16(stage + ARR_SZ + doff,     &g_Alo[gA]);
        cp16(stage + 2 * ARR_SZ + doff, &g_Whi[gW]);
        cp16(stage + 3 * ARR_SZ + doff, &g_Wlo[gW]);
    }
}

__global__ void __launch_bounds__(256)
gemm_mma_kernel() {
    extern __shared__ char smem[];
    const uint32_t sm = smem_u32(smem);
    const int t    = threadIdx.x;
    const int wid  = t >> 5;
    const int lane = t & 31;
    const int warpM = (wid & 3) * 32;       // 4 warps over M
    const int warpN = (wid >> 2) * 64;      // 2 warps over N
    const int rowBase = blockIdx.y * BM;
    const int colBase = blockIdx.x * BN;

    float acc[2][8][4];
    #pragma unroll
    for (int a = 0; a < 2; a++)
        #pragma unroll
        for (int b = 0; b < 8; b++)
            #pragma unroll
            for (int q = 0; q < 4; q++) acc[a][b][q] = 0.f;

    load_stage(sm, 0, 0, rowBase, colBase, t); CP_COMMIT();
    load_stage(sm, 1, 1, rowBase, colBase, t); CP_COMMIT();

    for (int k = 0; k < KITERS; k++) {
        const int p = k & 1;
        CP_WAIT1();
        __syncthreads();

        const uint32_t aHi = sm + p * STAGE_SZ;
        const uint32_t bHi = aHi + 2 * ARR_SZ;

        #pragma unroll
        for (int ks = 0; ks < 4; ks++) {
            uint32_t ah[2][4], al[2][4];
            #pragma unroll
            for (int mf = 0; mf < 2; mf++) {
                uint32_t ao = (uint32_t)((warpM + mf * 16 + (lane & 15)) * STRIDE_B
                                         + ks * 32 + (lane >> 4) * 16);
                ldsm4(ah[mf], aHi + ao);
                ldsm4(al[mf], aHi + ARR_SZ + ao);
            }
            #pragma unroll
            for (int np = 0; np < 4; np++) {
                uint32_t bh[4], bl[4];
                int n = warpN + np * 16 + (lane & 7) + ((lane >> 4) & 1) * 8;
                uint32_t bo = (uint32_t)(n * STRIDE_B + ks * 32 + ((lane >> 3) & 1) * 16);
                ldsm4(bh, bHi + bo);
                ldsm4(bl, bHi + ARR_SZ + bo);
                #pragma unroll
                for (int mf = 0; mf < 2; mf++) {
                    #pragma unroll
                    for (int nn = 0; nn < 2; nn++) {
                        float* C = acc[mf][np * 2 + nn];
                        mma16816(C, ah[mf], &bh[nn * 2]);   // hi*hi
                        mma16816(C, ah[mf], &bl[nn * 2]);   // hi*lo
                        mma16816(C, al[mf], &bh[nn * 2]);   // lo*hi
                    }
                }
            }
        }
        __syncthreads();
        if (k + 2 < KITERS) load_stage(sm, p, k + 2, rowBase, colBase, t);
        CP_COMMIT();
    }

    // ---- epilogue: d2 = w2 - 2*dot, per-row top-2 within this 128-col tile
    CP_WAIT0();
    __syncthreads();
    float* candV = (float*)smem;            // [128][4] (2 n-warps x 2)
    int*   candI = (int*)(smem + 2048);

    #pragma unroll
    for (int mf = 0; mf < 2; mf++) {
        #pragma unroll
        for (int half = 0; half < 2; half++) {
            float v1 = __int_as_float(0x7f800000), v2 = v1;
            int   i1 = 0x7fffffff,                i2 = i1;
            #pragma unroll
            for (int nf = 0; nf < 8; nf++) {
                #pragma unroll
                for (int q = 0; q < 2; q++) {
                    int col = colBase + warpN + nf * 8 + (lane & 3) * 2 + q;
                    float v = g_w2[col] - 2.f * acc[mf][nf][half * 2 + q];
                    merge2(v1, i1, v2, i2, v, col);
                }
            }
            #pragma unroll
            for (int x = 1; x <= 2; x <<= 1) {
                float ov1 = __shfl_xor_sync(0xffffffffu, v1, x);
                int   oi1 = __shfl_xor_sync(0xffffffffu, i1, x);
                float ov2 = __shfl_xor_sync(0xffffffffu, v2, x);
                int   oi2 = __shfl_xor_sync(0xffffffffu, i2, x);
                merge2(v1, i1, v2, i2, ov1, oi1);
                merge2(v1, i1, v2, i2, ov2, oi2);
            }
            if ((lane & 3) == 0) {
                int rowL = warpM + mf * 16 + half * 8 + (lane >> 2);
                int nw   = wid >> 2;
                candV[rowL * 4 + nw * 2 + 0] = v1;
                candI[rowL * 4 + nw * 2 + 0] = i1;
                candV[rowL * 4 + nw * 2 + 1] = v2;
                candI[rowL * 4 + nw * 2 + 1] = i2;
            }
        }
    }
    __syncthreads();

    if (t < BM) {
        float v1 = candV[t * 4], v2 = __int_as_float(0x7f800000);
        int   i1 = candI[t * 4], i2 = 0x7fffffff;
        #pragma unroll
        for (int s = 1; s < 4; s++) merge2(v1, i1, v2, i2, candV[t * 4 + s], candI[t * 4 + s]);
        int row = rowBase + t;
        int o = row * (NTILES * 2) + blockIdx.x * 2;
        g_tv[o] = v1;     g_ti[o] = i1;
        g_tv[o + 1] = v2; g_ti[o + 1] = i2;
    }
}

// ---------------------------------------------------------------------------
// Kernel 2: 4 batch rows per block. Warp w<4: reduce 64 candidates of row w ->
// approx top-2 -> exact fp32 recheck -> BMU. Then separable Gaussian tables and
// fully-coalesced streaming of 4 output rows (16KB).
// ---------------------------------------------------------------------------
__global__ void __launch_bounds__(256)
output_kernel(float* __restrict__ out,
              const float* __restrict__ batch,
              const float* __restrict__ weights,
              const int* __restrict__ decay_p,
              const int* __restrict__ it_p) {
    __shared__ float gx[4][GRID_N];
    __shared__ float gy[4][GRID_N];
    __shared__ int   s_bmu[4];

    const int t    = threadIdx.x;
    const int wid  = t >> 5;
    const int lane = t & 31;

    if (wid < 4) {
        const int b = blockIdx.x * 4 + wid;
        float v1 = g_tv[b * 64 + lane];
        int   i1 = g_ti[b * 64 + lane];
        float v2 = g_tv[b * 64 + 32 + lane];
        int   i2 = g_ti[b * 64 + 32 + lane];
        if (v2 < v1 || (v2 == v1 && i2 < i1)) {
            float tv = v1; v1 = v2; v2 = tv;
            int   ti = i1; i1 = i2; i2 = ti;
        }
        #pragma unroll
        for (int o = 16; o > 0; o >>= 1) {
            float ov1 = __shfl_xor_sync(0xffffffffu, v1, o);
            int   oi1 = __shfl_xor_sync(0xffffffffu, i1, o);
            float ov2 = __shfl_xor_sync(0xffffffffu, v2, o);
            int   oi2 = __shfl_xor_sync(0xffffffffu, i2, o);
            merge2(v1, i1, v2, i2, ov1, oi1);
            merge2(v1, i1, v2, i2, ov2, oi2);
        }
        // exact fp32 recheck of the two candidates
        const float* br = batch + (size_t)b * DIMK;
        const float* w0 = weights + (size_t)i1 * DIMK;
        const float* w1 = weights + (size_t)i2 * DIMK;
        float s0 = 0.f, s1 = 0.f;
        #pragma unroll 4
        for (int k = lane; k < DIMK; k += 32) {
            float x = br[k];
            s0 += x * w0[k];
            s1 += x * w1[k];
        }
        #pragma unroll
        for (int o = 16; o > 0; o >>= 1) {
            s0 += __shfl_down_sync(0xffffffffu, s0, o);
            s1 += __shfl_down_sync(0xffffffffu, s1, o);
        }
        if (lane == 0) {
            float d0 = g_w2[i1] - 2.f * s0;
            float d1 = g_w2[i2] - 2.f * s1;
            s_bmu[wid] = (d1 < d0 || (d1 == d0 && i2 < i1)) ? i2 : i1;
        }
    }
    __syncthreads();

    const float itv = (float)it_p[0];
    const float dcv = (float)decay_p[0];
    const float lr  = __expf(-itv / dcv);
    const float sig = 32.0f * lr;
    const float inv = 1.0f / (sig * sig);

    // 512 table entries (4 rows x 128), 2 per thread
    #pragma unroll
    for (int e = t; e < 512; e += 256) {
        int r = e >> 7;
        int x = e & 127;
        int bmu = s_bmu[r];
        if (x < GRID_N) {
            float d = (float)(x - (bmu >> 6));
            gx[r][x] = __expf(-d * d * inv);
        } else {
            int j = x - GRID_N;
            float d = (float)(j - (bmu & 63));
            gy[r][j] = __expf(-d * d * inv);
        }
    }
    __syncthreads();

    // coalesced stores: row r has 1024 float4; 256 threads x 4 chunks each
    #pragma unroll
    for (int r = 0; r < 4; r++) {
        float4* o4 = (float4*)(out + (size_t)(blockIdx.x * 4 + r) * MN_SZ);
        const float* gyr = gy[r];
        #pragma unroll
        for (int u = 0; u < 4; u++) {
            int f = u * 256 + t;            // float4 index within row
            int i = f >> 4;                 // grid row
            int j = (f & 15) * 4;           // grid col
            float gxi = gx[r][i];
            float4 v;
            v.x = gxi * gyr[j + 0];
            v.y = gxi * gyr[j + 1];
            v.z = gxi * gyr[j + 2];
            v.w = gxi * gyr[j + 3];
            o4[f] = v;
        }
    }
}

// ---------------------------------------------------------------------------
extern "C" void kernel_launch(void* const* d_in, const int* in_sizes, int n_in,
                              void* d_out, int out_size) {
    const float* batch   = (const float*)d_in[0];
    const float* weights = (const float*)d_in[1];
    const int* decay = (const int*)d_in[3];
    const int* it    = (const int*)d_in[4];
    float* out = (float*)d_out;

    cudaFuncSetAttribute(gemm_mma_kernel, cudaFuncAttributeMaxDynamicSharedMemorySize, SMEM_TOTAL);

    split_kernel<<<B_SZ * DIMK / 4 / 256, 256>>>(batch, weights);
    dim3 g(MN_SZ / BN, B_SZ / BM);     // (32, 32)
    gemm_mma_kernel<<<g, 256, SMEM_TOTAL>>>();
    output_kernel<<<B_SZ / 4, 256>>>(out, batch, weights, decay, it);
}

// round 14
// speedup vs baseline: 1.8172x; 1.7084x over previous
#include <cuda_runtime.h>
#include <cuda_bf16.h>
#include <cstdint>

// Problem constants
#define B_SZ   4096
#define DIMK   512
#define MN_SZ  4096
#define GRID_N 64
#define BM 128
#define BN 128
#define NTILES (MN_SZ / BN)        // 32 tiles -> 64 candidates/row
#define KC     64                  // K per stage (64 bf16 = 128B rows)
#define KITERS (DIMK / KC)         // 8

// smem: 2 arrays (Ahi, Whi), 128 rows x 64 bf16, stride 144B (conflict-free ldsm)
#define STRIDE_B 144
#define ARR_SZ   (128 * STRIDE_B)   // 18432
#define STAGE_SZ (2 * ARR_SZ)       // 36864
#define SMEM_TOTAL (2 * STAGE_SZ)   // 73728 -> 2-3 CTAs/SM

// ---- device scratch -------------------------------------------------------
__device__ float g_w2[MN_SZ];
__device__ __align__(16) __nv_bfloat16 g_Ahi[B_SZ * DIMK];
__device__ __align__(16) __nv_bfloat16 g_Whi[MN_SZ * DIMK];
__device__ float g_tv[B_SZ * NTILES * 2];
__device__ int   g_ti[B_SZ * NTILES * 2];

// ---- helpers --------------------------------------------------------------
__device__ __forceinline__ uint32_t smem_u32(const void* p) {
    uint32_t a;
    asm("{ .reg .u64 t; cvta.to.shared.u64 t, %1; cvt.u32.u64 %0, t; }" : "=r"(a) : "l"(p));
    return a;
}
__device__ __forceinline__ void cp16(uint32_t dst, const void* src) {
    asm volatile("cp.async.cg.shared.global [%0], [%1], 16;" :: "r"(dst), "l"(src));
}
#define CP_COMMIT() asm volatile("cp.async.commit_group;" ::: "memory")
#define CP_WAIT1()  asm volatile("cp.async.wait_group 1;" ::: "memory")
#define CP_WAIT0()  asm volatile("cp.async.wait_group 0;" ::: "memory")

__device__ __forceinline__ void ldsm4(uint32_t* r, uint32_t a) {
    asm volatile("ldmatrix.sync.aligned.m8n8.x4.shared.b16 {%0,%1,%2,%3}, [%4];"
                 : "=r"(r[0]), "=r"(r[1]), "=r"(r[2]), "=r"(r[3]) : "r"(a));
}
__device__ __forceinline__ void mma16816(float* c, const uint32_t* a, const uint32_t* b) {
    asm volatile("mma.sync.aligned.m16n8k16.row.col.f32.bf16.bf16.f32 "
                 "{%0,%1,%2,%3}, {%4,%5,%6,%7}, {%8,%9}, {%0,%1,%2,%3};"
                 : "+f"(c[0]), "+f"(c[1]), "+f"(c[2]), "+f"(c[3])
                 : "r"(a[0]), "r"(a[1]), "r"(a[2]), "r"(a[3]), "r"(b[0]), "r"(b[1]));
}
__device__ __forceinline__ void merge2(float& v1, int& i1, float& v2, int& i2,
                                       float ov, int oi) {
    if (ov < v1 || (ov == v1 && oi < i1)) { v2 = v1; i2 = i1; v1 = ov; i1 = oi; }
    else if (ov < v2 || (ov == v2 && oi < i2)) { v2 = ov; i2 = oi; }
}

// ---------------------------------------------------------------------------
// Kernel 0: fp32 -> bf16 (hi) for batch & weights, fused w2 (block = 2 rows)
// ---------------------------------------------------------------------------
__global__ void split_kernel(const float* __restrict__ a, const float* __restrict__ w) {
    __shared__ float s_part[8];
    const int tid = threadIdx.x;
    int i = blockIdx.x * 256 + tid;                   // float4 index
    float4 x = ((const float4*)a)[i];
    float4 y = ((const float4*)w)[i];
    ((__nv_bfloat162*)g_Ahi)[i * 2 + 0] = __nv_bfloat162(__float2bfloat16(x.x), __float2bfloat16(x.y));
    ((__nv_bfloat162*)g_Ahi)[i * 2 + 1] = __nv_bfloat162(__float2bfloat16(x.z), __float2bfloat16(x.w));
    ((__nv_bfloat162*)g_Whi)[i * 2 + 0] = __nv_bfloat162(__float2bfloat16(y.x), __float2bfloat16(y.y));
    ((__nv_bfloat162*)g_Whi)[i * 2 + 1] = __nv_bfloat162(__float2bfloat16(y.z), __float2bfloat16(y.w));

    float s = y.x * y.x + y.y * y.y + y.z * y.z + y.w * y.w;
    #pragma unroll
    for (int o = 16; o > 0; o >>= 1) s += __shfl_down_sync(0xffffffffu, s, o);
    if ((tid & 31) == 0) s_part[tid >> 5] = s;
    __syncthreads();
    if (tid == 0)
        g_w2[blockIdx.x * 2]     = s_part[0] + s_part[1] + s_part[2] + s_part[3];
    else if (tid == 128)
        g_w2[blockIdx.x * 2 + 1] = s_part[4] + s_part[5] + s_part[6] + s_part[7];
}

// ---------------------------------------------------------------------------
// Kernel 1: bf16 mma.sync GEMM (128x128 tile), 2-stage K=64 pipeline + top-2
// ---------------------------------------------------------------------------
__device__ __forceinline__ void load_stage(uint32_t smBase, int buf, int kIter,
                                           int rowBase, int colBase, int t) {
    uint32_t stage = smBase + buf * STAGE_SZ;
    #pragma unroll
    for (int i = 0; i < 4; i++) {
        int cid = i * 256 + t;          // 1024 16B-chunks per array
        int r = cid >> 3, c = cid & 7;
        uint32_t doff = (uint32_t)(r * STRIDE_B + c * 16);
        size_t gA = (size_t)(rowBase + r) * DIMK + kIter * KC + c * 8;
        size_t gW = (size_t)(colBase + r) * DIMK + kIter * KC + c * 8;
        cp16(stage + doff,          &g_Ahi[gA]);
        cp16(stage + ARR_SZ + doff, &g_Whi[gW]);
    }
}

__global__ void __launch_bounds__(256, 2)
gemm_mma_kernel() {
    extern __shared__ char smem[];
    const uint32_t sm = smem_u32(smem);
    const int t    = threadIdx.x;
    const int wid  = t >> 5;
    const int lane = t & 31;
    const int warpM = (wid & 3) * 32;       // 4 warps over M
    const int warpN = (wid >> 2) * 64;      // 2 warps over N
    const int rowBase = blockIdx.y * BM;
    const int colBase = blockIdx.x * BN;

    float acc[2][8][4];
    #pragma unroll
    for (int a = 0; a < 2; a++)
        #pragma unroll
        for (int b = 0; b < 8; b++)
            #pragma unroll
            for (int q = 0; q < 4; q++) acc[a][b][q] = 0.f;

    load_stage(sm, 0, 0, rowBase, colBase, t); CP_COMMIT();
    load_stage(sm, 1, 1, rowBase, colBase, t); CP_COMMIT();

    for (int k = 0; k < KITERS; k++) {
        const int p = k & 1;
        CP_WAIT1();
        __syncthreads();

        const uint32_t aHi = sm + p * STAGE_SZ;
        const uint32_t bHi = aHi + ARR_SZ;

        #pragma unroll
        for (int ks = 0; ks < 4; ks++) {
            uint32_t ah[2][4];
            #pragma unroll
            for (int mf = 0; mf < 2; mf++) {
                uint32_t ao = (uint32_t)((warpM + mf * 16 + (lane & 15)) * STRIDE_B
                                         + ks * 32 + (lane >> 4) * 16);
                ldsm4(ah[mf], aHi + ao);
            }
            #pragma unroll
            for (int np = 0; np < 4; np++) {
                uint32_t bh[4];
                int n = warpN + np * 16 + (lane & 7) + ((lane >> 4) & 1) * 8;
                uint32_t bo = (uint32_t)(n * STRIDE_B + ks * 32 + ((lane >> 3) & 1) * 16);
                ldsm4(bh, bHi + bo);
                #pragma unroll
                for (int mf = 0; mf < 2; mf++) {
                    #pragma unroll
                    for (int nn = 0; nn < 2; nn++)
                        mma16816(acc[mf][np * 2 + nn], ah[mf], &bh[nn * 2]);
                }
            }
        }
        __syncthreads();
        if (k + 2 < KITERS) load_stage(sm, p, k + 2, rowBase, colBase, t);
        CP_COMMIT();
    }

    // ---- epilogue: d2 = w2 - 2*dot, per-row top-2 within this 128-col tile
    CP_WAIT0();
    __syncthreads();
    float* candV = (float*)smem;            // [128][4] (2 n-warps x 2)
    int*   candI = (int*)(smem + 2048);

    #pragma unroll
    for (int mf = 0; mf < 2; mf++) {
        #pragma unroll
        for (int half = 0; half < 2; half++) {
            float v1 = __int_as_float(0x7f800000), v2 = v1;
            int   i1 = 0x7fffffff,                i2 = i1;
            #pragma unroll
            for (int nf = 0; nf < 8; nf++) {
                #pragma unroll
                for (int q = 0; q < 2; q++) {
                    int col = colBase + warpN + nf * 8 + (lane & 3) * 2 + q;
                    float v = g_w2[col] - 2.f * acc[mf][nf][half * 2 + q];
                    merge2(v1, i1, v2, i2, v, col);
                }
            }
            #pragma unroll
            for (int x = 1; x <= 2; x <<= 1) {
                float ov1 = __shfl_xor_sync(0xffffffffu, v1, x);
                int   oi1 = __shfl_xor_sync(0xffffffffu, i1, x);
                float ov2 = __shfl_xor_sync(0xffffffffu, v2, x);
                int   oi2 = __shfl_xor_sync(0xffffffffu, i2, x);
                merge2(v1, i1, v2, i2, ov1, oi1);
                merge2(v1, i1, v2, i2, ov2, oi2);
            }
            if ((lane & 3) == 0) {
                int rowL = warpM + mf * 16 + half * 8 + (lane >> 2);
                int nw   = wid >> 2;
                candV[rowL * 4 + nw * 2 + 0] = v1;
                candI[rowL * 4 + nw * 2 + 0] = i1;
                candV[rowL * 4 + nw * 2 + 1] = v2;
                candI[rowL * 4 + nw * 2 + 1] = i2;
            }
        }
    }
    __syncthreads();

    if (t < BM) {
        float v1 = candV[t * 4], v2 = __int_as_float(0x7f800000);
        int   i1 = candI[t * 4], i2 = 0x7fffffff;
        #pragma unroll
        for (int s = 1; s < 4; s++) merge2(v1, i1, v2, i2, candV[t * 4 + s], candI[t * 4 + s]);
        int row = rowBase + t;
        int o = row * (NTILES * 2) + blockIdx.x * 2;
        g_tv[o] = v1;     g_ti[o] = i1;
        g_tv[o + 1] = v2; g_ti[o + 1] = i2;
    }
}

// ---------------------------------------------------------------------------
// Kernel 2: 4 batch rows per block. Warp w<4: approx top-8 of 64 candidates ->
// exact fp32 recheck of all 8 -> BMU. Then Gaussian tables + coalesced stores.
// ---------------------------------------------------------------------------
__global__ void __launch_bounds__(256)
output_kernel(float* __restrict__ out,
              const float* __restrict__ batch,
              const float* __restrict__ weights,
              const int* __restrict__ decay_p,
              const int* __restrict__ it_p) {
    __shared__ float gx[4][GRID_N];
    __shared__ float gy[4][GRID_N];
    __shared__ int   s_bmu[4];

    const int t    = threadIdx.x;
    const int wid  = t >> 5;
    const int lane = t & 31;
    const float INF = __int_as_float(0x7f800000);

    if (wid < 4) {
        const int b = blockIdx.x * 4 + wid;
        float va = g_tv[b * 64 + lane];
        int   ia = g_ti[b * 64 + lane];
        float vb = g_tv[b * 64 + 32 + lane];
        int   ib = g_ti[b * 64 + 32 + lane];

        // extract approx top-8 by repeated warp-min + invalidate (idx unique)
        int cand[8];
        #pragma unroll
        for (int r = 0; r < 8; r++) {
            float mv = va; int mi = ia;
            if (vb < mv || (vb == mv && ib < mi)) { mv = vb; mi = ib; }
            #pragma unroll
            for (int o = 16; o > 0; o >>= 1) {
                float ov = __shfl_xor_sync(0xffffffffu, mv, o);
                int   oi = __shfl_xor_sync(0xffffffffu, mi, o);
                if (ov < mv || (ov == mv && oi < mi)) { mv = ov; mi = oi; }
            }
            cand[r] = mi;
            if (ia == mi) va = INF;
            if (ib == mi) vb = INF;
        }

        // exact fp32 dots for all 8 candidates
        const float* br = batch + (size_t)b * DIMK;
        float s[8];
        #pragma unroll
        for (int r = 0; r < 8; r++) s[r] = 0.f;
        for (int k = lane; k < DIMK; k += 32) {
            float x = br[k];
            #pragma unroll
            for (int r = 0; r < 8; r++)
                s[r] += x * weights[(size_t)cand[r] * DIMK + k];
        }
        #pragma unroll
        for (int o = 16; o > 0; o >>= 1) {
            #pragma unroll
            for (int r = 0; r < 8; r++)
                s[r] += __shfl_down_sync(0xffffffffu, s[r], o);
        }
        if (lane == 0) {
            float bv = INF; int bi = 0x7fffffff;
            #pragma unroll
            for (int r = 0; r < 8; r++) {
                float d = g_w2[cand[r]] - 2.f * s[r];
                if (d < bv || (d == bv && cand[r] < bi)) { bv = d; bi = cand[r]; }
            }
            s_bmu[wid] = bi;
        }
    }
    __syncthreads();

    const float itv = (float)it_p[0];
    const float dcv = (float)decay_p[0];
    const float lr  = __expf(-itv / dcv);
    const float sig = 32.0f * lr;
    const float inv = 1.0f / (sig * sig);

    // 512 table entries (4 rows x 128), 2 per thread
    #pragma unroll
    for (int e = t; e < 512; e += 256) {
        int r = e >> 7;
        int x = e & 127;
        int bmu = s_bmu[r];
        if (x < GRID_N) {
            float d = (float)(x - (bmu >> 6));
            gx[r][x] = __expf(-d * d * inv);
        } else {
            int j = x - GRID_N;
            float d = (float)(j - (bmu & 63));
            gy[r][j] = __expf(-d * d * inv);
        }
    }
    __syncthreads();

    // coalesced stores: row r has 1024 float4; 256 threads x 4 chunks each
    #pragma unroll
    for (int r = 0; r < 4; r++) {
        float4* o4 = (float4*)(out + (size_t)(blockIdx.x * 4 + r) * MN_SZ);
        const float* gyr = gy[r];
        #pragma unroll
        for (int u = 0; u < 4; u++) {
            int f = u * 256 + t;            // float4 index within row
            int i = f >> 4;                 // grid row
            int j = (f & 15) * 4;           // grid col
            float gxi = gx[r][i];
            float4 v;
            v.x = gxi * gyr[j + 0];
            v.y = gxi * gyr[j + 1];
            v.z = gxi * gyr[j + 2];
            v.w = gxi * gyr[j + 3];
            o4[f] = v;
        }
    }
}

// ---------------------------------------------------------------------------
extern "C" void kernel_launch(void* const* d_in, const int* in_sizes, int n_in,
                              void* d_out, int out_size) {
    const float* batch   = (const float*)d_in[0];
    const float* weights = (const float*)d_in[1];
    const int* decay = (const int*)d_in[3];
    const int* it    = (const int*)d_in[4];
    float* out = (float*)d_out;

    cudaFuncSetAttribute(gemm_mma_kernel, cudaFuncAttributeMaxDynamicSharedMemorySize, SMEM_TOTAL);

    split_kernel<<<B_SZ * DIMK / 4 / 256, 256>>>(batch, weights);
    dim3 g(MN_SZ / BN, B_SZ / BM);     // (32, 32)
    gemm_mma_kernel<<<g, 256, SMEM_TOTAL>>>();
    output_kernel<<<B_SZ / 4, 256>>>(out, batch, weights, decay, it);
}

// round 15
// speedup vs baseline: 2.1332x; 1.1739x over previous
#include <cuda_runtime.h>
#include <cuda_bf16.h>
#include <cstdint>

// Problem constants
#define B_SZ   4096
#define DIMK   512
#define MN_SZ  4096
#define GRID_N 64
#define BM 128
#define BN 128
#define NTILES (MN_SZ / BN)        // 32 tiles -> 64 candidates/row
#define KC     64                  // K per stage (64 bf16 = 128B rows)
#define KITERS (DIMK / KC)         // 8

// smem: 2 arrays (Ahi, Whi), 128 rows x 64 bf16, stride 144B (conflict-free ldsm)
#define STRIDE_B 144
#define ARR_SZ   (128 * STRIDE_B)   // 18432
#define STAGE_SZ (2 * ARR_SZ)       // 36864
#define NSTAGE   3
#define SMEM_TOTAL (NSTAGE * STAGE_SZ)   // 110592 -> 2 CTAs/SM (221KB of 228KB)

// ---- device scratch -------------------------------------------------------
__device__ float g_w2[MN_SZ];
__device__ __align__(16) __nv_bfloat16 g_Ahi[B_SZ * DIMK];
__device__ __align__(16) __nv_bfloat16 g_Whi[MN_SZ * DIMK];
__device__ float g_tv[B_SZ * NTILES * 2];
__device__ int   g_ti[B_SZ * NTILES * 2];

// ---- helpers --------------------------------------------------------------
__device__ __forceinline__ uint32_t smem_u32(const void* p) {
    uint32_t a;
    asm("{ .reg .u64 t; cvta.to.shared.u64 t, %1; cvt.u32.u64 %0, t; }" : "=r"(a) : "l"(p));
    return a;
}
__device__ __forceinline__ void cp16(uint32_t dst, const void* src) {
    asm volatile("cp.async.cg.shared.global [%0], [%1], 16;" :: "r"(dst), "l"(src));
}
#define CP_COMMIT() asm volatile("cp.async.commit_group;" ::: "memory")
#define CP_WAIT1()  asm volatile("cp.async.wait_group 1;" ::: "memory")
#define CP_WAIT0()  asm volatile("cp.async.wait_group 0;" ::: "memory")

__device__ __forceinline__ void ldsm4(uint32_t* r, uint32_t a) {
    asm volatile("ldmatrix.sync.aligned.m8n8.x4.shared.b16 {%0,%1,%2,%3}, [%4];"
                 : "=r"(r[0]), "=r"(r[1]), "=r"(r[2]), "=r"(r[3]) : "r"(a));
}
__device__ __forceinline__ void mma16816(float* c, const uint32_t* a, const uint32_t* b) {
    asm volatile("mma.sync.aligned.m16n8k16.row.col.f32.bf16.bf16.f32 "
                 "{%0,%1,%2,%3}, {%4,%5,%6,%7}, {%8,%9}, {%0,%1,%2,%3};"
                 : "+f"(c[0]), "+f"(c[1]), "+f"(c[2]), "+f"(c[3])
                 : "r"(a[0]), "r"(a[1]), "r"(a[2]), "r"(a[3]), "r"(b[0]), "r"(b[1]));
}
__device__ __forceinline__ void merge2(float& v1, int& i1, float& v2, int& i2,
                                       float ov, int oi) {
    if (ov < v1 || (ov == v1 && oi < i1)) { v2 = v1; i2 = i1; v1 = ov; i1 = oi; }
    else if (ov < v2 || (ov == v2 && oi < i2)) { v2 = ov; i2 = oi; }
}

// ---------------------------------------------------------------------------
// Kernel 0: fp32 -> bf16 (hi) for batch & weights, fused w2 (block = 2 rows)
// ---------------------------------------------------------------------------
__global__ void split_kernel(const float* __restrict__ a, const float* __restrict__ w) {
    __shared__ float s_part[8];
    const int tid = threadIdx.x;
    int i = blockIdx.x * 256 + tid;                   // float4 index
    float4 x = ((const float4*)a)[i];
    float4 y = ((const float4*)w)[i];
    ((__nv_bfloat162*)g_Ahi)[i * 2 + 0] = __nv_bfloat162(__float2bfloat16(x.x), __float2bfloat16(x.y));
    ((__nv_bfloat162*)g_Ahi)[i * 2 + 1] = __nv_bfloat162(__float2bfloat16(x.z), __float2bfloat16(x.w));
    ((__nv_bfloat162*)g_Whi)[i * 2 + 0] = __nv_bfloat162(__float2bfloat16(y.x), __float2bfloat16(y.y));
    ((__nv_bfloat162*)g_Whi)[i * 2 + 1] = __nv_bfloat162(__float2bfloat16(y.z), __float2bfloat16(y.w));

    float s = y.x * y.x + y.y * y.y + y.z * y.z + y.w * y.w;
    #pragma unroll
    for (int o = 16; o > 0; o >>= 1) s += __shfl_down_sync(0xffffffffu, s, o);
    if ((tid & 31) == 0) s_part[tid >> 5] = s;
    __syncthreads();
    if (tid == 0)
        g_w2[blockIdx.x * 2]     = s_part[0] + s_part[1] + s_part[2] + s_part[3];
    else if (tid == 128)
        g_w2[blockIdx.x * 2 + 1] = s_part[4] + s_part[5] + s_part[6] + s_part[7];
}

// ---------------------------------------------------------------------------
// Kernel 1: bf16 mma.sync GEMM (128x128 tile), 3-stage K=64 pipeline + top-2
// One barrier per k-iter: iter k loads buf (k+2)%3 == (k-1)%3, which every
// warp finished reading before this iter's top-of-loop barrier.
// ---------------------------------------------------------------------------
__device__ __forceinline__ void load_stage(uint32_t smBase, int buf, int kIter,
                                           int rowBase, int colBase, int t) {
    uint32_t stage = smBase + buf * STAGE_SZ;
    #pragma unroll
    for (int i = 0; i < 4; i++) {
        int cid = i * 256 + t;          // 1024 16B-chunks per array
        int r = cid >> 3, c = cid & 7;
        uint32_t doff = (uint32_t)(r * STRIDE_B + c * 16);
        size_t gA = (size_t)(rowBase + r) * DIMK + kIter * KC + c * 8;
        size_t gW = (size_t)(colBase + r) * DIMK + kIter * KC + c * 8;
        cp16(stage + doff,          &g_Ahi[gA]);
        cp16(stage + ARR_SZ + doff, &g_Whi[gW]);
    }
}

__global__ void __launch_bounds__(256, 2)
gemm_mma_kernel() {
    extern __shared__ char smem[];
    const uint32_t sm = smem_u32(smem);
    const int t    = threadIdx.x;
    const int wid  = t >> 5;
    const int lane = t & 31;
    const int warpM = (wid & 3) * 32;       // 4 warps over M
    const int warpN = (wid >> 2) * 64;      // 2 warps over N
    const int rowBase = blockIdx.y * BM;
    const int colBase = blockIdx.x * BN;

    float acc[2][8][4];
    #pragma unroll
    for (int a = 0; a < 2; a++)
        #pragma unroll
        for (int b = 0; b < 8; b++)
            #pragma unroll
            for (int q = 0; q < 4; q++) acc[a][b][q] = 0.f;

    load_stage(sm, 0, 0, rowBase, colBase, t); CP_COMMIT();
    load_stage(sm, 1, 1, rowBase, colBase, t); CP_COMMIT();

    #pragma unroll
    for (int k = 0; k < KITERS; k++) {
        CP_WAIT1();
        __syncthreads();   // stage k ready; all warps done with buf (k-1)%3

        const int p = k % 3;
        const uint32_t aHi = sm + p * STAGE_SZ;
        const uint32_t bHi = aHi + ARR_SZ;

        #pragma unroll
        for (int ks = 0; ks < 4; ks++) {
            uint32_t ah[2][4];
            #pragma unroll
            for (int mf = 0; mf < 2; mf++) {
                uint32_t ao = (uint32_t)((warpM + mf * 16 + (lane & 15)) * STRIDE_B
                                         + ks * 32 + (lane >> 4) * 16);
                ldsm4(ah[mf], aHi + ao);
            }
            #pragma unroll
            for (int np = 0; np < 4; np++) {
                uint32_t bh[4];
                int n = warpN + np * 16 + (lane & 7) + ((lane >> 4) & 1) * 8;
                uint32_t bo = (uint32_t)(n * STRIDE_B + ks * 32 + ((lane >> 3) & 1) * 16);
                ldsm4(bh, bHi + bo);
                #pragma unroll
                for (int mf = 0; mf < 2; mf++) {
                    #pragma unroll
                    for (int nn = 0; nn < 2; nn++)
                        mma16816(acc[mf][np * 2 + nn], ah[mf], &bh[nn * 2]);
                }
            }
        }
        if (k + 2 < KITERS) load_stage(sm, (k + 2) % 3, k + 2, rowBase, colBase, t);
        CP_COMMIT();
    }

    // ---- epilogue: d2 = w2 - 2*dot, per-row top-2 within this 128-col tile
    CP_WAIT0();
    __syncthreads();
    float* candV = (float*)smem;            // [128][4] (2 n-warps x 2)
    int*   candI = (int*)(smem + 2048);

    #pragma unroll
    for (int mf = 0; mf < 2; mf++) {
        #pragma unroll
        for (int half = 0; half < 2; half++) {
            float v1 = __int_as_float(0x7f800000), v2 = v1;
            int   i1 = 0x7fffffff,                i2 = i1;
            #pragma unroll
            for (int nf = 0; nf < 8; nf++) {
                #pragma unroll
                for (int q = 0; q < 2; q++) {
                    int col = colBase + warpN + nf * 8 + (lane & 3) * 2 + q;
                    float v = g_w2[col] - 2.f * acc[mf][nf][half * 2 + q];
                    merge2(v1, i1, v2, i2, v, col);
                }
            }
            #pragma unroll
            for (int x = 1; x <= 2; x <<= 1) {
                float ov1 = __shfl_xor_sync(0xffffffffu, v1, x);
                int   oi1 = __shfl_xor_sync(0xffffffffu, i1, x);
                float ov2 = __shfl_xor_sync(0xffffffffu, v2, x);
                int   oi2 = __shfl_xor_sync(0xffffffffu, i2, x);
                merge2(v1, i1, v2, i2, ov1, oi1);
                merge2(v1, i1, v2, i2, ov2, oi2);
            }
            if ((lane & 3) == 0) {
                int rowL = warpM + mf * 16 + half * 8 + (lane >> 2);
                int nw   = wid >> 2;
                candV[rowL * 4 + nw * 2 + 0] = v1;
                candI[rowL * 4 + nw * 2 + 0] = i1;
                candV[rowL * 4 + nw * 2 + 1] = v2;
                candI[rowL * 4 + nw * 2 + 1] = i2;
            }
        }
    }
    __syncthreads();

    if (t < BM) {
        float v1 = candV[t * 4], v2 = __int_as_float(0x7f800000);
        int   i1 = candI[t * 4], i2 = 0x7fffffff;
        #pragma unroll
        for (int s = 1; s < 4; s++) merge2(v1, i1, v2, i2, candV[t * 4 + s], candI[t * 4 + s]);
        int row = rowBase + t;
        int o = row * (NTILES * 2) + blockIdx.x * 2;
        g_tv[o] = v1;     g_ti[o] = i1;
        g_tv[o + 1] = v2; g_ti[o + 1] = i2;
    }
}

// ---------------------------------------------------------------------------
// Kernel 2: 8 batch rows per block (all 8 warps busy). Warp w: approx top-8 of
// 64 candidates -> exact fp32 recheck of all 8 -> BMU. Then Gaussian tables +
// coalesced stores of 8 rows (32KB).
// ---------------------------------------------------------------------------
__global__ void __launch_bounds__(256)
output_kernel(float* __restrict__ out,
              const float* __restrict__ batch,
              const float* __restrict__ weights,
              const int* __restrict__ decay_p,
              const int* __restrict__ it_p) {
    __shared__ float gx[8][GRID_N];
    __shared__ float gy[8][GRID_N];
    __shared__ int   s_bmu[8];

    const int t    = threadIdx.x;
    const int wid  = t >> 5;
    const int lane = t & 31;
    const float INF = __int_as_float(0x7f800000);

    {
        const int b = blockIdx.x * 8 + wid;
        float va = g_tv[b * 64 + lane];
        int   ia = g_ti[b * 64 + lane];
        float vb = g_tv[b * 64 + 32 + lane];
        int   ib = g_ti[b * 64 + 32 + lane];

        // extract approx top-8 by repeated warp-min + invalidate (idx unique)
        int cand[8];
        #pragma unroll
        for (int r = 0; r < 8; r++) {
            float mv = va; int mi = ia;
            if (vb < mv || (vb == mv && ib < mi)) { mv = vb; mi = ib; }
            #pragma unroll
            for (int o = 16; o > 0; o >>= 1) {
                float ov = __shfl_xor_sync(0xffffffffu, mv, o);
                int   oi = __shfl_xor_sync(0xffffffffu, mi, o);
                if (ov < mv || (ov == mv && oi < mi)) { mv = ov; mi = oi; }
            }
            cand[r] = mi;
            if (ia == mi) va = INF;
            if (ib == mi) vb = INF;
        }

        // exact fp32 dots for all 8 candidates
        const float* br = batch + (size_t)b * DIMK;
        float s[8];
        #pragma unroll
        for (int r = 0; r < 8; r++) s[r] = 0.f;
        for (int k = lane; k < DIMK; k += 32) {
            float x = br[k];
            #pragma unroll
            for (int r = 0; r < 8; r++)
                s[r] += x * weights[(size_t)cand[r] * DIMK + k];
        }
        #pragma unroll
        for (int o = 16; o > 0; o >>= 1) {
            #pragma unroll
            for (int r = 0; r < 8; r++)
                s[r] += __shfl_down_sync(0xffffffffu, s[r], o);
        }
        if (lane == 0) {
            float bv = INF; int bi = 0x7fffffff;
            #pragma unroll
            for (int r = 0; r < 8; r++) {
                float d = g_w2[cand[r]] - 2.f * s[r];
                if (d < bv || (d == bv && cand[r] < bi)) { bv = d; bi = cand[r]; }
            }
            s_bmu[wid] = bi;
        }
    }
    __syncthreads();

    const float itv = (float)it_p[0];
    const float dcv = (float)decay_p[0];
    const float lr  = __expf(-itv / dcv);
    const float sig = 32.0f * lr;
    const float inv = 1.0f / (sig * sig);

    // 1024 table entries (8 rows x 128), 4 per thread
    #pragma unroll
    for (int e = t; e < 1024; e += 256) {
        int r = e >> 7;
        int x = e & 127;
        int bmu = s_bmu[r];
        if (x < GRID_N) {
            float d = (float)(x - (bmu >> 6));
            gx[r][x] = __expf(-d * d * inv);
        } else {
            int j = x - GRID_N;
            float d = (float)(j - (bmu & 63));
            gy[r][j] = __expf(-d * d * inv);
        }
    }
    __syncthreads();

    // coalesced stores: row r has 1024 float4; 256 threads x 4 chunks per row
    #pragma unroll
    for (int r = 0; r < 8; r++) {
        float4* o4 = (float4*)(out + (size_t)(blockIdx.x * 8 + r) * MN_SZ);
        const float* gyr = gy[r];
        #pragma unroll
        for (int u = 0; u < 4; u++) {
            int f = u * 256 + t;            // float4 index within row
            int i = f >> 4;                 // grid row
            int j = (f & 15) * 4;           // grid col
            float gxi = gx[r][i];
            float4 v;
            v.x = gxi * gyr[j + 0];
            v.y = gxi * gyr[j + 1];
            v.z = gxi * gyr[j + 2];
            v.w = gxi * gyr[j + 3];
            o4[f] = v;
        }
    }
}

// ---------------------------------------------------------------------------
extern "C" void kernel_launch(void* const* d_in, const int* in_sizes, int n_in,
                              void* d_out, int out_size) {
    const float* batch   = (const float*)d_in[0];
    const float* weights = (const float*)d_in[1];
    const int* decay = (const int*)d_in[3];
    const int* it    = (const int*)d_in[4];
    float* out = (float*)d_out;

    cudaFuncSetAttribute(gemm_mma_kernel, cudaFuncAttributeMaxDynamicSharedMemorySize, SMEM_TOTAL);

    split_kernel<<<B_SZ * DIMK / 4 / 256, 256>>>(batch, weights);
    dim3 g(MN_SZ / BN, B_SZ / BM);     // (32, 32)
    gemm_mma_kernel<<<g, 256, SMEM_TOTAL>>>();
    output_kernel<<<B_SZ / 8, 256>>>(out, batch, weights, decay, it);
}